// round 2
// baseline (speedup 1.0000x reference)
#include <cuda_runtime.h>
#include <cuda_bf16.h>
#include <math.h>

// ---------------------------------------------------------------------------
// Decoder_15187004358874: MAT decoder, fp32 baseline v2 (vectorized SGEMM).
// B=256, N=64, D=512, H=8, HD=64, NB=4, A=64. M = B*N = 16384.
// ---------------------------------------------------------------------------

#define M_ROWS 16384
#define DMODEL 512

// 6 scratch buffers of [16384 x 512] fp32
__device__ float g_scratch[6ull * M_ROWS * DMODEL];

__device__ __forceinline__ float gelu_f(float x) {
    return 0.5f * x * (1.0f + erff(x * 0.7071067811865476f));
}

// ---------------------------------------------------------------------------
// Vectorized SGEMM: C[M,N] = A[M,K] @ W[K,N] (+bias)(+gelu).
// 128x128 tile, BK=16, 256 threads, TM=TN=8, float4 global loads.
// Requires: M%128==0, K%16==0, N%4==0, pointers 16B-aligned.
// ---------------------------------------------------------------------------
#define BM 128
#define BN 128
#define BKV 16
#define TM 8
#define TN 8

template <int ACT>
__global__ void __launch_bounds__(256, 2) sgemm_v4_kernel(
    const float* __restrict__ A, const float* __restrict__ W,
    const float* __restrict__ bias, float* __restrict__ C,
    int M, int N, int K)
{
    __shared__ float As[BKV][BM];
    __shared__ float Bs[BKV][BN];

    const int tid = threadIdx.x;
    const int bn0 = blockIdx.x * BN;
    const int bm0 = blockIdx.y * BM;
    const int tr = (tid / 16) * TM;
    const int tc = (tid % 16) * TN;

    float acc[TM][TN];
    #pragma unroll
    for (int i = 0; i < TM; i++)
        #pragma unroll
        for (int j = 0; j < TN; j++) acc[i][j] = 0.f;

    for (int k0 = 0; k0 < K; k0 += BKV) {
        // A tile: 128 rows x 16 k = 512 float4, 2 per thread.
        #pragma unroll
        for (int it = 0; it < 2; it++) {
            int idx = it * 256 + tid;          // 0..511
            int row = idx >> 2;                // 0..127
            int kq  = (idx & 3) * 4;           // 0,4,8,12
            float4 a4 = *(const float4*)&A[(size_t)(bm0 + row) * K + k0 + kq];
            As[kq + 0][row] = a4.x;
            As[kq + 1][row] = a4.y;
            As[kq + 2][row] = a4.z;
            As[kq + 3][row] = a4.w;
        }
        // W tile: 16 k x 128 n = 512 float4, 2 per thread.
        #pragma unroll
        for (int it = 0; it < 2; it++) {
            int idx = it * 256 + tid;          // 0..511
            int kk  = idx >> 5;                // 0..15
            int nq  = (idx & 31) * 4;          // 0..124
            int nn  = bn0 + nq;
            float4 w4 = (nn < N)
                ? *(const float4*)&W[(size_t)(k0 + kk) * N + nn]
                : make_float4(0.f, 0.f, 0.f, 0.f);
            *(float4*)&Bs[kk][nq] = w4;
        }
        __syncthreads();

        #pragma unroll
        for (int k = 0; k < BKV; k++) {
            float rm[TM], rn[TN];
            #pragma unroll
            for (int i = 0; i < TM; i++) rm[i] = As[k][tr + i];
            #pragma unroll
            for (int j = 0; j < TN; j++) rn[j] = Bs[k][tc + j];
            #pragma unroll
            for (int i = 0; i < TM; i++)
                #pragma unroll
                for (int j = 0; j < TN; j++)
                    acc[i][j] += rm[i] * rn[j];
        }
        __syncthreads();
    }

    #pragma unroll
    for (int i = 0; i < TM; i++) {
        int row = bm0 + tr + i;
        #pragma unroll
        for (int j = 0; j < TN; j++) {
            int col = bn0 + tc + j;
            if (col < N) {
                float v = acc[i][j];
                if (bias) v += bias[col];
                if (ACT == 1) v = gelu_f(v);
                C[(size_t)row * N + col] = v;
            }
        }
    }
}

// ---------------------------------------------------------------------------
// Scalar SGEMM fallback (used only for K=65 encoder GEMM).
// ---------------------------------------------------------------------------
#define BKS 8

template <int ACT>
__global__ void __launch_bounds__(256, 2) sgemm_s_kernel(
    const float* __restrict__ A, const float* __restrict__ W,
    const float* __restrict__ bias, float* __restrict__ C,
    int M, int N, int K)
{
    __shared__ float As[BKS][BM];
    __shared__ float Bs[BKS][BN];

    const int tid = threadIdx.x;
    const int bn0 = blockIdx.x * BN;
    const int bm0 = blockIdx.y * BM;
    const int tr = (tid / 16) * TM;
    const int tc = (tid % 16) * TN;

    float acc[TM][TN];
    #pragma unroll
    for (int i = 0; i < TM; i++)
        #pragma unroll
        for (int j = 0; j < TN; j++) acc[i][j] = 0.f;

    const int aRow = tid >> 1;
    const int aCol = (tid & 1) * 4;
    const int bRow = tid >> 5;
    const int bCol = (tid & 31) * 4;

    for (int k0 = 0; k0 < K; k0 += BKS) {
        #pragma unroll
        for (int j = 0; j < 4; j++) {
            int kk = k0 + aCol + j;
            As[aCol + j][aRow] = (kk < K) ? A[(size_t)(bm0 + aRow) * K + kk] : 0.f;
        }
        #pragma unroll
        for (int j = 0; j < 4; j++) {
            int kk = k0 + bRow;
            int nn = bn0 + bCol + j;
            Bs[bRow][bCol + j] = (kk < K && nn < N) ? W[(size_t)kk * N + nn] : 0.f;
        }
        __syncthreads();

        #pragma unroll
        for (int k = 0; k < BKS; k++) {
            float rm[TM], rn[TN];
            #pragma unroll
            for (int i = 0; i < TM; i++) rm[i] = As[k][tr + i];
            #pragma unroll
            for (int j = 0; j < TN; j++) rn[j] = Bs[k][tc + j];
            #pragma unroll
            for (int i = 0; i < TM; i++)
                #pragma unroll
                for (int j = 0; j < TN; j++)
                    acc[i][j] += rm[i] * rn[j];
        }
        __syncthreads();
    }

    #pragma unroll
    for (int i = 0; i < TM; i++) {
        int row = bm0 + tr + i;
        #pragma unroll
        for (int j = 0; j < TN; j++) {
            int col = bn0 + tc + j;
            if (col < N) {
                float v = acc[i][j];
                if (bias) v += bias[col];
                if (ACT == 1) v = gelu_f(v);
                C[(size_t)row * N + col] = v;
            }
        }
    }
}

// ---------------------------------------------------------------------------
// Fused attention: one block per (b,h). 64x64 q/k/v tiles in SMEM,
// scores -> causal softmax -> AV. Q smem buffer reused for the att matrix.
// Dynamic smem: 3 * 64 * 68 * 4 = 52224 bytes.
// ---------------------------------------------------------------------------
#define APAD 68

__global__ void __launch_bounds__(256) attn_kernel(
    const float* __restrict__ q, const float* __restrict__ k,
    const float* __restrict__ v, float* __restrict__ y)
{
    extern __shared__ float sm[];
    float* sq  = sm;                 // [64][APAD]  (later reused for att)
    float* skT = sm + 64 * APAD;     // [64][APAD]  skT[kk][key]
    float* sv  = sm + 2 * 64 * APAD; // [64][APAD]  sv[key][dim]

    const int bh = blockIdx.x;
    const int b = bh >> 3, h = bh & 7;
    const size_t base = ((size_t)b * 64) * DMODEL + (size_t)h * 64;
    const int tid = threadIdx.x;

    for (int i = tid; i < 4096; i += 256) {
        int r = i >> 6, c = i & 63;
        float qv = q[base + (size_t)r * DMODEL + c];
        float kv = k[base + (size_t)r * DMODEL + c];
        float vv = v[base + (size_t)r * DMODEL + c];
        sq[r * APAD + c]  = qv;
        skT[c * APAD + r] = kv;   // transposed
        sv[r * APAD + c]  = vv;
    }
    __syncthreads();

    const int r  = tid >> 2;        // query row 0..63
    const int c0 = (tid & 3) * 16;  // 16 keys/cols per thread

    float acc[16];
    #pragma unroll
    for (int j = 0; j < 16; j++) acc[j] = 0.f;

    for (int kk = 0; kk < 64; kk++) {
        float qv = sq[r * APAD + kk];
        #pragma unroll
        for (int j = 0; j < 16; j++)
            acc[j] += qv * skT[kk * APAD + c0 + j];
    }

    // scale + causal mask + softmax over the row (4 threads per row)
    float mx = -1e30f;
    #pragma unroll
    for (int j = 0; j < 16; j++) {
        int c = c0 + j;
        acc[j] = (c <= r) ? acc[j] * 0.125f : -1e30f;
        mx = fmaxf(mx, acc[j]);
    }
    mx = fmaxf(mx, __shfl_xor_sync(0xFFFFFFFFu, mx, 1));
    mx = fmaxf(mx, __shfl_xor_sync(0xFFFFFFFFu, mx, 2));

    float sum = 0.f;
    #pragma unroll
    for (int j = 0; j < 16; j++) {
        acc[j] = expf(acc[j] - mx);
        sum += acc[j];
    }
    sum += __shfl_xor_sync(0xFFFFFFFFu, sum, 1);
    sum += __shfl_xor_sync(0xFFFFFFFFu, sum, 2);
    float inv = 1.f / sum;

    __syncthreads();  // everyone done reading sq before overwrite
    #pragma unroll
    for (int j = 0; j < 16; j++)
        sq[r * APAD + c0 + j] = acc[j] * inv;
    __syncthreads();

    float out[16];
    #pragma unroll
    for (int j = 0; j < 16; j++) out[j] = 0.f;
    for (int kk = 0; kk < 64; kk++) {
        float a = sq[r * APAD + kk];
        #pragma unroll
        for (int j = 0; j < 16; j++)
            out[j] += a * sv[kk * APAD + c0 + j];
    }
    #pragma unroll
    for (int j = 0; j < 16; j++)
        y[base + (size_t)r * DMODEL + c0 + j] = out[j];
}

// ---------------------------------------------------------------------------
// Fused (x + res) -> LayerNorm. One block (128 threads) per row of 512.
// ---------------------------------------------------------------------------
__global__ void __launch_bounds__(128) add_ln_kernel(
    const float* __restrict__ x, const float* __restrict__ res,
    const float* __restrict__ g, const float* __restrict__ bb,
    float* __restrict__ out)
{
    const int row = blockIdx.x;
    const int tid = threadIdx.x;
    const float* xr = x + (size_t)row * DMODEL;
    const float* rr = res ? res + (size_t)row * DMODEL : nullptr;

    float v[4];
    float s = 0.f;
    #pragma unroll
    for (int i = 0; i < 4; i++) {
        int c = tid + i * 128;
        float t = xr[c];
        if (rr) t += rr[c];
        v[i] = t;
        s += t;
    }

    __shared__ float red[4];
    #pragma unroll
    for (int o = 16; o; o >>= 1) s += __shfl_xor_sync(0xFFFFFFFFu, s, o);
    if ((tid & 31) == 0) red[tid >> 5] = s;
    __syncthreads();
    s = red[0] + red[1] + red[2] + red[3];
    const float mu = s * (1.f / 512.f);

    float var = 0.f;
    #pragma unroll
    for (int i = 0; i < 4; i++) {
        float d = v[i] - mu;
        var += d * d;
    }
    #pragma unroll
    for (int o = 16; o; o >>= 1) var += __shfl_xor_sync(0xFFFFFFFFu, var, o);
    __syncthreads();
    if ((tid & 31) == 0) red[tid >> 5] = var;
    __syncthreads();
    var = (red[0] + red[1] + red[2] + red[3]) * (1.f / 512.f);
    const float rs = rsqrtf(var + 1e-5f);

    #pragma unroll
    for (int i = 0; i < 4; i++) {
        int c = tid + i * 128;
        out[(size_t)row * DMODEL + c] = (v[i] - mu) * rs * g[c] + bb[c];
    }
}

// ---------------------------------------------------------------------------
// Host orchestration
// ---------------------------------------------------------------------------
static void launch_gemm(const float* A, const float* W, const float* bias,
                        float* C, int M, int N, int K, int act)
{
    dim3 grid((N + BN - 1) / BN, (M + BM - 1) / BM);
    if ((K & 15) == 0 && (N & 3) == 0) {
        if (act) sgemm_v4_kernel<1><<<grid, 256>>>(A, W, bias, C, M, N, K);
        else     sgemm_v4_kernel<0><<<grid, 256>>>(A, W, bias, C, M, N, K);
    } else {
        if (act) sgemm_s_kernel<1><<<grid, 256>>>(A, W, bias, C, M, N, K);
        else     sgemm_s_kernel<0><<<grid, 256>>>(A, W, bias, C, M, N, K);
    }
}

extern "C" void kernel_launch(void* const* d_in, const int* in_sizes, int n_in,
                              void* d_out, int out_size)
{
    const float* action   = (const float*)d_in[0];   // [B,N,65]
    const float* obs_rep  = (const float*)d_in[1];   // [B,N,512]
    /* d_in[2] = obs (unused) */
    const float* w_ae     = (const float*)d_in[3];   // [65,512]
    const float* ln0_g    = (const float*)d_in[4];
    const float* ln0_b    = (const float*)d_in[5];
    const float* blk_ln_g = (const float*)d_in[6];   // [4,3,512]
    const float* blk_ln_b = (const float*)d_in[7];
    const float* blk_wq   = (const float*)d_in[8];   // [4,2,512,512]
    const float* blk_wk   = (const float*)d_in[9];
    const float* blk_wv   = (const float*)d_in[10];
    const float* blk_wp   = (const float*)d_in[11];
    const float* blk_bq   = (const float*)d_in[12];  // [4,2,512]
    const float* blk_bk   = (const float*)d_in[13];
    const float* blk_bv   = (const float*)d_in[14];
    const float* blk_bp   = (const float*)d_in[15];
    const float* blk_w1   = (const float*)d_in[16];  // [4,512,512]
    const float* blk_b1   = (const float*)d_in[17];  // [4,512]
    const float* blk_w2   = (const float*)d_in[18];
    const float* blk_b2   = (const float*)d_in[19];
    const float* wh1      = (const float*)d_in[20];  // [512,512]
    const float* bh1      = (const float*)d_in[21];
    const float* lnh_g    = (const float*)d_in[22];
    const float* lnh_b    = (const float*)d_in[23];
    const float* wh2      = (const float*)d_in[24];  // [512,64]
    const float* bh2      = (const float*)d_in[25];  // [64]

    float* sc = nullptr;
    cudaGetSymbolAddress((void**)&sc, g_scratch);
    const size_t S = (size_t)M_ROWS * DMODEL;
    float* X  = sc;
    float* Qb = sc + 1 * S;
    float* Kb = sc + 2 * S;
    float* Vb = sc + 3 * S;
    float* Yb = sc + 4 * S;
    float* Tb = sc + 5 * S;

    const int attn_smem = 3 * 64 * APAD * 4;  // 52224
    static bool attr_set = false;
    if (!attr_set) {
        cudaFuncSetAttribute(attn_kernel,
                             cudaFuncAttributeMaxDynamicSharedMemorySize, attn_smem);
        attr_set = true;
    }

    const int M = M_ROWS, D = DMODEL;
    const size_t DD = (size_t)D * D;

    // encoder: x = LN(gelu(action @ w_ae))
    launch_gemm(action, w_ae, nullptr, Tb, M, D, 65, 1);
    add_ln_kernel<<<M, 128>>>(Tb, nullptr, ln0_g, ln0_b, X);

    for (int i = 0; i < 4; i++) {
        const float* wq0 = blk_wq + ((size_t)i * 2 + 0) * DD;
        const float* wk0 = blk_wk + ((size_t)i * 2 + 0) * DD;
        const float* wv0 = blk_wv + ((size_t)i * 2 + 0) * DD;
        const float* wp0 = blk_wp + ((size_t)i * 2 + 0) * DD;
        const float* bq0 = blk_bq + ((size_t)i * 2 + 0) * D;
        const float* bk0 = blk_bk + ((size_t)i * 2 + 0) * D;
        const float* bv0 = blk_bv + ((size_t)i * 2 + 0) * D;
        const float* bp0 = blk_bp + ((size_t)i * 2 + 0) * D;
        const float* wq1 = blk_wq + ((size_t)i * 2 + 1) * DD;
        const float* wk1 = blk_wk + ((size_t)i * 2 + 1) * DD;
        const float* wv1 = blk_wv + ((size_t)i * 2 + 1) * DD;
        const float* wp1 = blk_wp + ((size_t)i * 2 + 1) * DD;
        const float* bq1 = blk_bq + ((size_t)i * 2 + 1) * D;
        const float* bk1 = blk_bk + ((size_t)i * 2 + 1) * D;
        const float* bv1 = blk_bv + ((size_t)i * 2 + 1) * D;
        const float* bp1 = blk_bp + ((size_t)i * 2 + 1) * D;
        const float* g0 = blk_ln_g + ((size_t)i * 3 + 0) * D;
        const float* b0 = blk_ln_b + ((size_t)i * 3 + 0) * D;
        const float* g1 = blk_ln_g + ((size_t)i * 3 + 1) * D;
        const float* b1 = blk_ln_b + ((size_t)i * 3 + 1) * D;
        const float* g2 = blk_ln_g + ((size_t)i * 3 + 2) * D;
        const float* b2 = blk_ln_b + ((size_t)i * 3 + 2) * D;
        const float* w1 = blk_w1 + (size_t)i * DD;
        const float* bias1 = blk_b1 + (size_t)i * D;
        const float* w2 = blk_w2 + (size_t)i * DD;
        const float* bias2 = blk_b2 + (size_t)i * D;

        // sublayer 1: masked self-attn + residual + LN
        launch_gemm(X, wq0, bq0, Qb, M, D, D, 0);
        launch_gemm(X, wk0, bk0, Kb, M, D, D, 0);
        launch_gemm(X, wv0, bv0, Vb, M, D, D, 0);
        attn_kernel<<<2048, 256, attn_smem>>>(Qb, Kb, Vb, Yb);
        launch_gemm(Yb, wp0, bp0, Tb, M, D, D, 0);
        add_ln_kernel<<<M, 128>>>(Tb, X, g0, b0, X);

        // sublayer 2: masked cross-attn (q=obs_rep, k=v=x), residual obs_rep
        launch_gemm(obs_rep, wq1, bq1, Qb, M, D, D, 0);
        launch_gemm(X, wk1, bk1, Kb, M, D, D, 0);
        launch_gemm(X, wv1, bv1, Vb, M, D, D, 0);
        attn_kernel<<<2048, 256, attn_smem>>>(Qb, Kb, Vb, Yb);
        launch_gemm(Yb, wp1, bp1, Tb, M, D, D, 0);
        add_ln_kernel<<<M, 128>>>(Tb, obs_rep, g1, b1, X);

        // sublayer 3: GELU MLP + residual + LN
        launch_gemm(X, w1, bias1, Qb, M, D, D, 1);
        launch_gemm(Qb, w2, bias2, Tb, M, D, D, 0);
        add_ln_kernel<<<M, 128>>>(Tb, X, g2, b2, X);
    }

    // head: LN(gelu(x @ wh1 + bh1)) @ wh2 + bh2
    launch_gemm(X, wh1, bh1, Tb, M, D, D, 1);
    add_ln_kernel<<<M, 128>>>(Tb, nullptr, lnh_g, lnh_b, Qb);
    launch_gemm(Qb, wh2, bh2, (float*)d_out, M, 64, D, 0);
}

// round 4
// speedup vs baseline: 1.1344x; 1.1344x over previous
#include <cuda_runtime.h>
#include <cuda_bf16.h>
#include <math.h>
#include <stdint.h>

// ---------------------------------------------------------------------------
// Decoder_15187004358874 — bf16-split (Markidis) GEMMs via mma.sync HMMA.
// tcgen05 unavailable (harness PTX targets sm_103 without 'a' suffix).
// B=256, N=64, D=512, H=8, HD=64, NB=4. M = 16384.
// C = Ah*Bh^T + Ah*Bl^T + Al*Bh^T, fp32 accumulate.
// ---------------------------------------------------------------------------

#define M_ROWS 16384
#define DMODEL 512
#define DD 262144  // 512*512

// ---------------- scratch (static __device__, no allocs) -------------------
__device__ float g_X[M_ROWS * DMODEL];
__device__ float g_Q[M_ROWS * DMODEL];
__device__ float g_K[M_ROWS * DMODEL];
__device__ float g_V[M_ROWS * DMODEL];
__device__ float g_Y[M_ROWS * DMODEL];
__device__ __nv_bfloat16 g_Ph[M_ROWS * DMODEL];
__device__ __nv_bfloat16 g_Pl[M_ROWS * DMODEL];
__device__ __nv_bfloat16 g_P2h[M_ROWS * DMODEL];
__device__ __nv_bfloat16 g_P2l[M_ROWS * DMODEL];
__device__ __nv_bfloat16 g_Oh[M_ROWS * DMODEL];
__device__ __nv_bfloat16 g_Ol[M_ROWS * DMODEL];
__device__ __nv_bfloat16 g_Wh[42ull * DD];
__device__ __nv_bfloat16 g_Wl[42ull * DD];
__device__ __nv_bfloat16 g_AEh[M_ROWS * 128];
__device__ __nv_bfloat16 g_AEl[M_ROWS * 128];
__device__ __nv_bfloat16 g_WAEh[512 * 128];
__device__ __nv_bfloat16 g_WAEl[512 * 128];

// ---------------- helpers ---------------------------------------------------
__device__ __forceinline__ float gelu_f(float x) {
    return 0.5f * x * (1.0f + erff(x * 0.7071067811865476f));
}
__device__ __forceinline__ void split_bf16(float x, __nv_bfloat16& h, __nv_bfloat16& l) {
    h = __float2bfloat16_rn(x);
    l = __float2bfloat16_rn(x - __bfloat162float(h));
}
__device__ __forceinline__ uint32_t smem_u32(const void* p) {
    uint32_t a;
    asm("{ .reg .u64 t; cvta.to.shared.u64 t, %1; cvt.u32.u64 %0, t; }"
        : "=r"(a) : "l"(p));
    return a;
}

#define CP_ASYNC16(saddr, gaddr) \
    asm volatile("cp.async.cg.shared.global [%0], [%1], 16;" \
                 :: "r"(saddr), "l"(gaddr))
#define CP_COMMIT()  asm volatile("cp.async.commit_group;")
#define CP_WAIT1()   asm volatile("cp.async.wait_group 1;")
#define CP_WAIT0()   asm volatile("cp.async.wait_group 0;")

#define LDSM4(d, addr) \
    asm volatile("ldmatrix.sync.aligned.m8n8.x4.shared.b16 {%0,%1,%2,%3}, [%4];" \
                 : "=r"((d)[0]), "=r"((d)[1]), "=r"((d)[2]), "=r"((d)[3]) \
                 : "r"(addr))

#define MMA16816(cf, a, b0_, b1_) \
    asm volatile("mma.sync.aligned.m16n8k16.row.col.f32.bf16.bf16.f32 " \
                 "{%0,%1,%2,%3}, {%4,%5,%6,%7}, {%8,%9}, {%0,%1,%2,%3};" \
                 : "+f"((cf)[0]), "+f"((cf)[1]), "+f"((cf)[2]), "+f"((cf)[3]) \
                 : "r"((a)[0]), "r"((a)[1]), "r"((a)[2]), "r"((a)[3]), \
                   "r"(b0_), "r"(b1_))

// ---------------------------------------------------------------------------
// HMMA split-GEMM. BM=128, BK=32, 8 warps (4m x 2n), warp tile 32 x (BN/2).
// A: [M,K] bf16 (hi,lo). B: [N,K] bf16 (hi,lo; pre-transposed weights).
// SMEM tiles padded to 40 bf16 (80B) per row; 3-stage cp.async pipeline.
// ---------------------------------------------------------------------------
template <int BN_, int ACT, int OUT_PAIR>
__global__ void __launch_bounds__(256) hmma_gemm_kernel(
    const __nv_bfloat16* __restrict__ Ah, const __nv_bfloat16* __restrict__ Al,
    const __nv_bfloat16* __restrict__ Bh, const __nv_bfloat16* __restrict__ Bl,
    const float* __restrict__ bias,
    float* __restrict__ C, __nv_bfloat16* __restrict__ Ch, __nv_bfloat16* __restrict__ Cl,
    int M, int N, int K)
{
    constexpr int BM_ = 128;
    constexpr int WCOLS = BN_ / 2;      // cols per warp (64 or 32)
    constexpr int NJ = WCOLS / 8;       // n8 atoms per warp (8 or 4)
    constexpr int NT = NJ / 2;          // n16 ldmatrix tiles (4 or 2)
    constexpr int LDT = 80;             // smem row stride bytes (40 bf16)
    constexpr int A_BYTES = BM_ * LDT;
    constexpr int B_BYTES = BN_ * LDT;
    constexpr int STAGE = 2 * A_BYTES + 2 * B_BYTES;

    extern __shared__ __align__(128) char smem[];
    const uint32_t sb = smem_u32(smem);

    const int tid = threadIdx.x;
    const int wid = tid >> 5;
    const int lane = tid & 31;
    const int wm = wid >> 1;            // 0..3
    const int wn = wid & 1;             // 0..1

    const int bm0 = blockIdx.y * BM_;
    const int bn0 = blockIdx.x * BN_;
    const int NK = K >> 5;              // BK = 32

    const char* gAh = (const char*)(Ah + (size_t)bm0 * K);
    const char* gAl = (const char*)(Al + (size_t)bm0 * K);
    const char* gBh = (const char*)(Bh + (size_t)bn0 * K);
    const char* gBl = (const char*)(Bl + (size_t)bn0 * K);
    const int ldg = K * 2;              // bytes per row (A and B)

    auto load_stage = [&](int slot, int kc) {
        const uint32_t s0 = sb + slot * STAGE;
        const int kb = kc * 64;         // 32 bf16 = 64 bytes
        #pragma unroll
        for (int it = 0; it < 2; it++) {            // A: 128 rows x 4 chunks
            int idx = it * 256 + tid;
            int r = idx >> 2, c = (idx & 3) * 16;
            uint32_t so = s0 + r * LDT + c;
            CP_ASYNC16(so, gAh + (size_t)r * ldg + kb + c);
            CP_ASYNC16(so + A_BYTES, gAl + (size_t)r * ldg + kb + c);
        }
        #pragma unroll
        for (int it = 0; it < BN_ / 64; it++) {     // B: BN_ rows x 4 chunks
            int idx = it * 256 + tid;
            int r = idx >> 2, c = (idx & 3) * 16;
            uint32_t so = s0 + 2 * A_BYTES + r * LDT + c;
            CP_ASYNC16(so, gBh + (size_t)r * ldg + kb + c);
            CP_ASYNC16(so + B_BYTES, gBl + (size_t)r * ldg + kb + c);
        }
    };

    // ldmatrix lane offsets (within tile)
    const uint32_t aLaneOff =
        (uint32_t)((wm * 32 + (lane & 15)) * LDT + (lane >> 4) * 16);
    const uint32_t bLaneOff =
        (uint32_t)((wn * WCOLS + (lane & 7) + ((lane >> 4) << 3)) * LDT +
                   (((lane >> 3) & 1) << 4));

    float c[2][NJ][4];
    #pragma unroll
    for (int mi = 0; mi < 2; mi++)
        #pragma unroll
        for (int nj = 0; nj < NJ; nj++)
            #pragma unroll
            for (int q = 0; q < 4; q++) c[mi][nj][q] = 0.f;

    // prologue: stages 0,1
    load_stage(0, 0);
    CP_COMMIT();
    if (1 < NK) load_stage(1, 1);
    CP_COMMIT();

    for (int kc = 0; kc < NK; kc++) {
        CP_WAIT1();
        __syncthreads();

        int kn = kc + 2;
        if (kn < NK) load_stage(kn % 3, kn);
        CP_COMMIT();

        const int slot = kc % 3;
        const uint32_t aB = sb + slot * STAGE + aLaneOff;
        const uint32_t bB = sb + slot * STAGE + 2 * A_BYTES + bLaneOff;

        #pragma unroll
        for (int kh = 0; kh < 2; kh++) {
            const uint32_t ko = kh * 32;
            uint32_t ah[2][4], al[2][4];
            #pragma unroll
            for (int mi = 0; mi < 2; mi++) {
                LDSM4(ah[mi], aB + mi * 16 * LDT + ko);
                LDSM4(al[mi], aB + A_BYTES + mi * 16 * LDT + ko);
            }
            uint32_t bh[NT][4], bl[NT][4];
            #pragma unroll
            for (int t = 0; t < NT; t++) {
                LDSM4(bh[t], bB + t * 16 * LDT + ko);
                LDSM4(bl[t], bB + B_BYTES + t * 16 * LDT + ko);
            }
            #pragma unroll
            for (int mi = 0; mi < 2; mi++)
                #pragma unroll
                for (int t = 0; t < NT; t++) {
                    MMA16816(c[mi][2 * t + 0], ah[mi], bh[t][0], bh[t][1]);
                    MMA16816(c[mi][2 * t + 1], ah[mi], bh[t][2], bh[t][3]);
                    MMA16816(c[mi][2 * t + 0], ah[mi], bl[t][0], bl[t][1]);
                    MMA16816(c[mi][2 * t + 1], ah[mi], bl[t][2], bl[t][3]);
                    MMA16816(c[mi][2 * t + 0], al[mi], bh[t][0], bh[t][1]);
                    MMA16816(c[mi][2 * t + 1], al[mi], bh[t][2], bh[t][3]);
                }
        }
        __syncthreads();
    }

    CP_WAIT0();
    __syncthreads();

    // ---- epilogue: frags -> smem (pad 33) -> coalesced global ----
    float* eb = (float*)smem;  // [128][33]
    for (int c0 = 0; c0 < BN_; c0 += 32) {
        if (wn == c0 / WCOLS) {
            const int njb = (c0 % WCOLS) >> 3;
            #pragma unroll
            for (int mi = 0; mi < 2; mi++)
                #pragma unroll
                for (int j = 0; j < 4; j++) {
                    int nj = njb + j;
                    int row = wm * 32 + mi * 16 + (lane >> 2);
                    int col = wn * WCOLS + nj * 8 + (lane & 3) * 2 - c0;
                    eb[row * 33 + col]           = c[mi][nj][0];
                    eb[row * 33 + col + 1]       = c[mi][nj][1];
                    eb[(row + 8) * 33 + col]     = c[mi][nj][2];
                    eb[(row + 8) * 33 + col + 1] = c[mi][nj][3];
                }
        }
        __syncthreads();
        #pragma unroll
        for (int it = 0; it < 16; it++) {
            int idx = it * 256 + tid;
            int r = idx >> 5, cc = idx & 31;
            float v = eb[r * 33 + cc];
            int col = bn0 + c0 + cc;
            if (bias) v += bias[col];
            if (ACT == 1) v = gelu_f(v);
            size_t gi = (size_t)(bm0 + r) * N + col;
            if (OUT_PAIR) {
                __nv_bfloat16 h, l;
                split_bf16(v, h, l);
                Ch[gi] = h;
                Cl[gi] = l;
            } else {
                C[gi] = v;
            }
        }
        __syncthreads();
    }
}

// ---------------------------------------------------------------------------
// Weight prep: transpose [512,N] fp32 -> [N,512] bf16 hi/lo, 42 matrices.
// ---------------------------------------------------------------------------
__global__ void __launch_bounds__(256) wprep_kernel(
    const float* __restrict__ wq, const float* __restrict__ wk,
    const float* __restrict__ wv, const float* __restrict__ wp,
    const float* __restrict__ w1, const float* __restrict__ w2,
    const float* __restrict__ wh1, const float* __restrict__ wh2,
    __nv_bfloat16* __restrict__ oh, __nv_bfloat16* __restrict__ ol)
{
    const int z = blockIdx.z;
    const float* src;
    int N = 512;
    if (z < 32) {
        int i = z >> 3, j = z & 7, half = j >> 2, wsel = j & 3;
        const float* base = (wsel == 0) ? wq : (wsel == 1) ? wk : (wsel == 2) ? wv : wp;
        src = base + ((size_t)i * 2 + half) * DD;
    } else if (z < 40) {
        int i = (z - 32) >> 1;
        src = (((z - 32) & 1) ? w2 : w1) + (size_t)i * DD;
    } else if (z == 40) {
        src = wh1;
    } else {
        src = wh2;
        N = 64;
    }
    const int n0 = blockIdx.x * 32, k0 = blockIdx.y * 32;
    if (n0 >= N) return;

    __shared__ float t[32][33];
    const int lx = threadIdx.x & 31, ly = threadIdx.x >> 5;
    for (int r = ly; r < 32; r += 8)
        t[r][lx] = src[(size_t)(k0 + r) * N + n0 + lx];
    __syncthreads();
    const size_t slot = (size_t)z * DD;
    for (int r = ly; r < 32; r += 8) {
        float x = t[lx][r];
        __nv_bfloat16 h, l;
        split_bf16(x, h, l);
        oh[slot + (size_t)(n0 + r) * 512 + k0 + lx] = h;
        ol[slot + (size_t)(n0 + r) * 512 + k0 + lx] = l;
    }
}

__global__ void wae_prep_kernel(const float* __restrict__ w,
                                __nv_bfloat16* __restrict__ oh,
                                __nv_bfloat16* __restrict__ ol)
{
    int idx = blockIdx.x * 256 + threadIdx.x;
    if (idx >= 512 * 128) return;
    int n = idx >> 7, k = idx & 127;
    float x = (k < 65) ? w[(size_t)k * 512 + n] : 0.f;
    __nv_bfloat16 h, l;
    split_bf16(x, h, l);
    oh[idx] = h;
    ol[idx] = l;
}

__global__ void act_prep_kernel(const float* __restrict__ a,
                                __nv_bfloat16* __restrict__ oh,
                                __nv_bfloat16* __restrict__ ol)
{
    int idx = blockIdx.x * 256 + threadIdx.x;
    if (idx >= M_ROWS * 128) return;
    int m = idx >> 7, k = idx & 127;
    float x = (k < 65) ? a[(size_t)m * 65 + k] : 0.f;
    __nv_bfloat16 h, l;
    split_bf16(x, h, l);
    oh[idx] = h;
    ol[idx] = l;
}

__global__ void split_pair_kernel(const float4* __restrict__ in,
                                  __nv_bfloat162* __restrict__ oh,
                                  __nv_bfloat162* __restrict__ ol, int n4)
{
    int i = blockIdx.x * 256 + threadIdx.x;
    if (i >= n4) return;
    float4 x = in[i];
    __nv_bfloat16 h0, l0, h1, l1, h2, l2, h3, l3;
    split_bf16(x.x, h0, l0);
    split_bf16(x.y, h1, l1);
    split_bf16(x.z, h2, l2);
    split_bf16(x.w, h3, l3);
    oh[i * 2 + 0] = __nv_bfloat162(h0, h1);
    oh[i * 2 + 1] = __nv_bfloat162(h2, h3);
    ol[i * 2 + 0] = __nv_bfloat162(l0, l1);
    ol[i * 2 + 1] = __nv_bfloat162(l2, l3);
}

// ---------------------------------------------------------------------------
// Fused attention: one block per (b,h), 64x64 tile, fp32 SIMT.
// ---------------------------------------------------------------------------
#define APAD 68

__global__ void __launch_bounds__(256) attn_kernel(
    const float* __restrict__ q, const float* __restrict__ k,
    const float* __restrict__ v, float* __restrict__ y)
{
    extern __shared__ float sm[];
    float* sq  = sm;
    float* skT = sm + 64 * APAD;
    float* sv  = sm + 2 * 64 * APAD;

    const int bh = blockIdx.x;
    const int b = bh >> 3, h = bh & 7;
    const size_t base = ((size_t)b * 64) * DMODEL + (size_t)h * 64;
    const int tid = threadIdx.x;

    for (int i = tid; i < 4096; i += 256) {
        int r = i >> 6, c = i & 63;
        sq[r * APAD + c]  = q[base + (size_t)r * DMODEL + c];
        skT[c * APAD + r] = k[base + (size_t)r * DMODEL + c];
        sv[r * APAD + c]  = v[base + (size_t)r * DMODEL + c];
    }
    __syncthreads();

    const int r  = tid >> 2;
    const int c0 = (tid & 3) * 16;

    float acc[16];
    #pragma unroll
    for (int j = 0; j < 16; j++) acc[j] = 0.f;
    for (int kk = 0; kk < 64; kk++) {
        float qv = sq[r * APAD + kk];
        #pragma unroll
        for (int j = 0; j < 16; j++)
            acc[j] += qv * skT[kk * APAD + c0 + j];
    }

    float mx = -1e30f;
    #pragma unroll
    for (int j = 0; j < 16; j++) {
        int c = c0 + j;
        acc[j] = (c <= r) ? acc[j] * 0.125f : -1e30f;
        mx = fmaxf(mx, acc[j]);
    }
    mx = fmaxf(mx, __shfl_xor_sync(0xFFFFFFFFu, mx, 1));
    mx = fmaxf(mx, __shfl_xor_sync(0xFFFFFFFFu, mx, 2));

    float sum = 0.f;
    #pragma unroll
    for (int j = 0; j < 16; j++) {
        acc[j] = expf(acc[j] - mx);
        sum += acc[j];
    }
    sum += __shfl_xor_sync(0xFFFFFFFFu, sum, 1);
    sum += __shfl_xor_sync(0xFFFFFFFFu, sum, 2);
    float inv = 1.f / sum;

    __syncthreads();
    #pragma unroll
    for (int j = 0; j < 16; j++)
        sq[r * APAD + c0 + j] = acc[j] * inv;
    __syncthreads();

    float out[16];
    #pragma unroll
    for (int j = 0; j < 16; j++) out[j] = 0.f;
    for (int kk = 0; kk < 64; kk++) {
        float a = sq[r * APAD + kk];
        #pragma unroll
        for (int j = 0; j < 16; j++)
            out[j] += a * sv[kk * APAD + c0 + j];
    }
    #pragma unroll
    for (int j = 0; j < 16; j++)
        y[base + (size_t)r * DMODEL + c0 + j] = out[j];
}

// ---------------------------------------------------------------------------
// Fused (x+res) -> LayerNorm, writes fp32 + bf16 hi/lo pair.
// ---------------------------------------------------------------------------
__global__ void __launch_bounds__(128) add_ln_kernel(
    const float* __restrict__ x, const float* __restrict__ res,
    const float* __restrict__ g, const float* __restrict__ bb,
    float* __restrict__ out,
    __nv_bfloat16* __restrict__ oh, __nv_bfloat16* __restrict__ ol)
{
    const int row = blockIdx.x;
    const int tid = threadIdx.x;
    const float* xr = x + (size_t)row * DMODEL;
    const float* rr = res ? res + (size_t)row * DMODEL : nullptr;

    float v[4];
    float s = 0.f;
    #pragma unroll
    for (int i = 0; i < 4; i++) {
        int c = tid + i * 128;
        float t = xr[c];
        if (rr) t += rr[c];
        v[i] = t;
        s += t;
    }

    __shared__ float red[4];
    #pragma unroll
    for (int o = 16; o; o >>= 1) s += __shfl_xor_sync(0xFFFFFFFFu, s, o);
    if ((tid & 31) == 0) red[tid >> 5] = s;
    __syncthreads();
    s = red[0] + red[1] + red[2] + red[3];
    const float mu = s * (1.f / 512.f);

    float var = 0.f;
    #pragma unroll
    for (int i = 0; i < 4; i++) {
        float d = v[i] - mu;
        var += d * d;
    }
    #pragma unroll
    for (int o = 16; o; o >>= 1) var += __shfl_xor_sync(0xFFFFFFFFu, var, o);
    __syncthreads();
    if ((tid & 31) == 0) red[tid >> 5] = var;
    __syncthreads();
    var = (red[0] + red[1] + red[2] + red[3]) * (1.f / 512.f);
    const float rs = rsqrtf(var + 1e-5f);

    #pragma unroll
    for (int i = 0; i < 4; i++) {
        int c = tid + i * 128;
        float val = (v[i] - mu) * rs * g[c] + bb[c];
        size_t gi = (size_t)row * DMODEL + c;
        out[gi] = val;
        __nv_bfloat16 h, l;
        split_bf16(val, h, l);
        oh[gi] = h;
        ol[gi] = l;
    }
}

// ---------------------------------------------------------------------------
// Host orchestration
// ---------------------------------------------------------------------------
template <int BN_, int ACT, int OUT_PAIR>
static void launch_hmma(const __nv_bfloat16* Ah, const __nv_bfloat16* Al,
                        const __nv_bfloat16* Bh, const __nv_bfloat16* Bl,
                        const float* bias, float* C,
                        __nv_bfloat16* Ch, __nv_bfloat16* Cl,
                        int M, int N, int K)
{
    constexpr int STAGE = (2 * 128 + 2 * BN_) * 80;
    const int sbytes = 3 * STAGE;
    cudaFuncSetAttribute(hmma_gemm_kernel<BN_, ACT, OUT_PAIR>,
                         cudaFuncAttributeMaxDynamicSharedMemorySize, sbytes);
    dim3 grid(N / BN_, M / 128);
    hmma_gemm_kernel<BN_, ACT, OUT_PAIR><<<grid, 256, sbytes>>>(
        Ah, Al, Bh, Bl, bias, C, Ch, Cl, M, N, K);
}

extern "C" void kernel_launch(void* const* d_in, const int* in_sizes, int n_in,
                              void* d_out, int out_size)
{
    const float* action   = (const float*)d_in[0];
    const float* obs_rep  = (const float*)d_in[1];
    const float* w_ae     = (const float*)d_in[3];
    const float* ln0_g    = (const float*)d_in[4];
    const float* ln0_b    = (const float*)d_in[5];
    const float* blk_ln_g = (const float*)d_in[6];
    const float* blk_ln_b = (const float*)d_in[7];
    const float* blk_wq   = (const float*)d_in[8];
    const float* blk_wk   = (const float*)d_in[9];
    const float* blk_wv   = (const float*)d_in[10];
    const float* blk_wp   = (const float*)d_in[11];
    const float* blk_bq   = (const float*)d_in[12];
    const float* blk_bk   = (const float*)d_in[13];
    const float* blk_bv   = (const float*)d_in[14];
    const float* blk_bp   = (const float*)d_in[15];
    const float* blk_w1   = (const float*)d_in[16];
    const float* blk_b1   = (const float*)d_in[17];
    const float* blk_w2   = (const float*)d_in[18];
    const float* blk_b2   = (const float*)d_in[19];
    const float* wh1      = (const float*)d_in[20];
    const float* bh1      = (const float*)d_in[21];
    const float* lnh_g    = (const float*)d_in[22];
    const float* lnh_b    = (const float*)d_in[23];
    const float* wh2      = (const float*)d_in[24];
    const float* bh2      = (const float*)d_in[25];

    float *X, *Q, *Kb, *V, *Y;
    __nv_bfloat16 *Ph, *Pl, *P2h, *P2l, *Oh, *Ol, *Wh, *Wl, *AEh, *AEl, *WAEh, *WAEl;
    cudaGetSymbolAddress((void**)&X, g_X);
    cudaGetSymbolAddress((void**)&Q, g_Q);
    cudaGetSymbolAddress((void**)&Kb, g_K);
    cudaGetSymbolAddress((void**)&V, g_V);
    cudaGetSymbolAddress((void**)&Y, g_Y);
    cudaGetSymbolAddress((void**)&Ph, g_Ph);
    cudaGetSymbolAddress((void**)&Pl, g_Pl);
    cudaGetSymbolAddress((void**)&P2h, g_P2h);
    cudaGetSymbolAddress((void**)&P2l, g_P2l);
    cudaGetSymbolAddress((void**)&Oh, g_Oh);
    cudaGetSymbolAddress((void**)&Ol, g_Ol);
    cudaGetSymbolAddress((void**)&Wh, g_Wh);
    cudaGetSymbolAddress((void**)&Wl, g_Wl);
    cudaGetSymbolAddress((void**)&AEh, g_AEh);
    cudaGetSymbolAddress((void**)&AEl, g_AEl);
    cudaGetSymbolAddress((void**)&WAEh, g_WAEh);
    cudaGetSymbolAddress((void**)&WAEl, g_WAEl);

    const int attn_smem = 3 * 64 * APAD * 4;
    cudaFuncSetAttribute(attn_kernel,
                         cudaFuncAttributeMaxDynamicSharedMemorySize, attn_smem);

    const int M = M_ROWS, D = DMODEL;
    const int n4 = M * D / 4;

    // ---- prep: weights + padded encoder operands + obs_rep pair ----
    {
        dim3 g(16, 16, 42);
        wprep_kernel<<<g, 256>>>(blk_wq, blk_wk, blk_wv, blk_wp,
                                 blk_w1, blk_w2, wh1, wh2, Wh, Wl);
        wae_prep_kernel<<<(512 * 128 + 255) / 256, 256>>>(w_ae, WAEh, WAEl);
        act_prep_kernel<<<(M * 128 + 255) / 256, 256>>>(action, AEh, AEl);
        split_pair_kernel<<<(n4 + 255) / 256, 256>>>(
            (const float4*)obs_rep, (__nv_bfloat162*)Oh, (__nv_bfloat162*)Ol, n4);
    }

    // ---- encoder: X = LN(gelu(action @ w_ae)) ----
    launch_hmma<128, 1, 0>(AEh, AEl, WAEh, WAEl, nullptr, Q, nullptr, nullptr, M, D, 128);
    add_ln_kernel<<<M, 128>>>(Q, nullptr, ln0_g, ln0_b, X, Ph, Pl);

    for (int i = 0; i < 4; i++) {
        const __nv_bfloat16* wq0h = Wh + (size_t)(i * 8 + 0) * DD;
        const __nv_bfloat16* wq0l = Wl + (size_t)(i * 8 + 0) * DD;
        const __nv_bfloat16* wk0h = Wh + (size_t)(i * 8 + 1) * DD;
        const __nv_bfloat16* wk0l = Wl + (size_t)(i * 8 + 1) * DD;
        const __nv_bfloat16* wv0h = Wh + (size_t)(i * 8 + 2) * DD;
        const __nv_bfloat16* wv0l = Wl + (size_t)(i * 8 + 2) * DD;
        const __nv_bfloat16* wp0h = Wh + (size_t)(i * 8 + 3) * DD;
        const __nv_bfloat16* wp0l = Wl + (size_t)(i * 8 + 3) * DD;
        const __nv_bfloat16* wq1h = Wh + (size_t)(i * 8 + 4) * DD;
        const __nv_bfloat16* wq1l = Wl + (size_t)(i * 8 + 4) * DD;
        const __nv_bfloat16* wk1h = Wh + (size_t)(i * 8 + 5) * DD;
        const __nv_bfloat16* wk1l = Wl + (size_t)(i * 8 + 5) * DD;
        const __nv_bfloat16* wv1h = Wh + (size_t)(i * 8 + 6) * DD;
        const __nv_bfloat16* wv1l = Wl + (size_t)(i * 8 + 6) * DD;
        const __nv_bfloat16* wp1h = Wh + (size_t)(i * 8 + 7) * DD;
        const __nv_bfloat16* wp1l = Wl + (size_t)(i * 8 + 7) * DD;
        const __nv_bfloat16* w1h  = Wh + (size_t)(32 + i * 2) * DD;
        const __nv_bfloat16* w1l  = Wl + (size_t)(32 + i * 2) * DD;
        const __nv_bfloat16* w2h  = Wh + (size_t)(33 + i * 2) * DD;
        const __nv_bfloat16* w2l  = Wl + (size_t)(33 + i * 2) * DD;

        const float* bq0 = blk_bq + ((size_t)i * 2 + 0) * D;
        const float* bk0 = blk_bk + ((size_t)i * 2 + 0) * D;
        const float* bv0 = blk_bv + ((size_t)i * 2 + 0) * D;
        const float* bp0 = blk_bp + ((size_t)i * 2 + 0) * D;
        const float* bq1 = blk_bq + ((size_t)i * 2 + 1) * D;
        const float* bk1 = blk_bk + ((size_t)i * 2 + 1) * D;
        const float* bv1 = blk_bv + ((size_t)i * 2 + 1) * D;
        const float* bp1 = blk_bp + ((size_t)i * 2 + 1) * D;
        const float* g0 = blk_ln_g + ((size_t)i * 3 + 0) * D;
        const float* b0 = blk_ln_b + ((size_t)i * 3 + 0) * D;
        const float* g1 = blk_ln_g + ((size_t)i * 3 + 1) * D;
        const float* b1 = blk_ln_b + ((size_t)i * 3 + 1) * D;
        const float* g2 = blk_ln_g + ((size_t)i * 3 + 2) * D;
        const float* b2 = blk_ln_b + ((size_t)i * 3 + 2) * D;
        const float* bias1 = blk_b1 + (size_t)i * D;
        const float* bias2 = blk_b2 + (size_t)i * D;

        // sublayer 1: self-attn
        launch_hmma<128, 0, 0>(Ph, Pl, wq0h, wq0l, bq0, Q, nullptr, nullptr, M, D, D);
        launch_hmma<128, 0, 0>(Ph, Pl, wk0h, wk0l, bk0, Kb, nullptr, nullptr, M, D, D);
        launch_hmma<128, 0, 0>(Ph, Pl, wv0h, wv0l, bv0, V, nullptr, nullptr, M, D, D);
        attn_kernel<<<2048, 256, attn_smem>>>(Q, Kb, V, Y);
        split_pair_kernel<<<(n4 + 255) / 256, 256>>>(
            (const float4*)Y, (__nv_bfloat162*)Ph, (__nv_bfloat162*)Pl, n4);
        launch_hmma<128, 0, 0>(Ph, Pl, wp0h, wp0l, bp0, Q, nullptr, nullptr, M, D, D);
        add_ln_kernel<<<M, 128>>>(Q, X, g0, b0, X, Ph, Pl);

        // sublayer 2: cross-attn (q = obs_rep)
        launch_hmma<128, 0, 0>(Oh, Ol, wq1h, wq1l, bq1, Q, nullptr, nullptr, M, D, D);
        launch_hmma<128, 0, 0>(Ph, Pl, wk1h, wk1l, bk1, Kb, nullptr, nullptr, M, D, D);
        launch_hmma<128, 0, 0>(Ph, Pl, wv1h, wv1l, bv1, V, nullptr, nullptr, M, D, D);
        attn_kernel<<<2048, 256, attn_smem>>>(Q, Kb, V, Y);
        split_pair_kernel<<<(n4 + 255) / 256, 256>>>(
            (const float4*)Y, (__nv_bfloat162*)Ph, (__nv_bfloat162*)Pl, n4);
        launch_hmma<128, 0, 0>(Ph, Pl, wp1h, wp1l, bp1, Q, nullptr, nullptr, M, D, D);
        add_ln_kernel<<<M, 128>>>(Q, obs_rep, g1, b1, X, Ph, Pl);

        // sublayer 3: MLP
        launch_hmma<128, 1, 1>(Ph, Pl, w1h, w1l, bias1, nullptr, P2h, P2l, M, D, D);
        launch_hmma<128, 0, 0>(P2h, P2l, w2h, w2l, bias2, Q, nullptr, nullptr, M, D, D);
        add_ln_kernel<<<M, 128>>>(Q, X, g2, b2, X, Ph, Pl);
    }

    // head
    const __nv_bfloat16* wh1h = Wh + (size_t)40 * DD;
    const __nv_bfloat16* wh1l = Wl + (size_t)40 * DD;
    const __nv_bfloat16* wh2h = Wh + (size_t)41 * DD;
    const __nv_bfloat16* wh2l = Wl + (size_t)41 * DD;
    launch_hmma<128, 1, 0>(Ph, Pl, wh1h, wh1l, bh1, Q, nullptr, nullptr, M, D, D);
    add_ln_kernel<<<M, 128>>>(Q, nullptr, lnh_g, lnh_b, Kb, Ph, Pl);
    launch_hmma<64, 0, 0>(Ph, Pl, wh2h, wh2l, bh2, (float*)d_out, nullptr, nullptr, M, 64, D);
}

// round 7
// speedup vs baseline: 1.1768x; 1.0373x over previous
#include <cuda_runtime.h>
#include <cuda_bf16.h>
#include <math.h>
#include <stdint.h>

// ---------------------------------------------------------------------------
// Decoder_15187004358874 — bf16-split (Markidis) GEMMs via mma.sync HMMA.
// R7 = R5 change set (2-stage pipeline @ 2 blocks/SM, fused QKV/KV GEMMs)
//      + attention kernel writes bf16 split pair directly (no split_pair pass).
// B=256, N=64, D=512, H=8, HD=64, NB=4. M = 16384.
// C = Ah*Bh^T + Ah*Bl^T + Al*Bh^T, fp32 accumulate.
// ---------------------------------------------------------------------------

#define M_ROWS 16384
#define DMODEL 512
#define DD 262144  // 512*512

// ---------------- scratch (static __device__, no allocs) -------------------
__device__ float g_X[M_ROWS * DMODEL];
__device__ float g_T[M_ROWS * DMODEL];
__device__ float g_Q1[M_ROWS * DMODEL];
__device__ float g_QKV[M_ROWS * 1536];
__device__ __nv_bfloat16 g_Ph[M_ROWS * DMODEL];
__device__ __nv_bfloat16 g_Pl[M_ROWS * DMODEL];
__device__ __nv_bfloat16 g_P2h[M_ROWS * DMODEL];
__device__ __nv_bfloat16 g_P2l[M_ROWS * DMODEL];
__device__ __nv_bfloat16 g_Oh[M_ROWS * DMODEL];
__device__ __nv_bfloat16 g_Ol[M_ROWS * DMODEL];
__device__ __nv_bfloat16 g_Wh[42ull * DD];
__device__ __nv_bfloat16 g_Wl[42ull * DD];
__device__ __nv_bfloat16 g_AEh[M_ROWS * 128];
__device__ __nv_bfloat16 g_AEl[M_ROWS * 128];
__device__ __nv_bfloat16 g_WAEh[512 * 128];
__device__ __nv_bfloat16 g_WAEl[512 * 128];
__device__ float g_CatB[8 * 1536];

// ---------------- helpers ---------------------------------------------------
__device__ __forceinline__ float gelu_f(float x) {
    return 0.5f * x * (1.0f + erff(x * 0.7071067811865476f));
}
__device__ __forceinline__ void split_bf16(float x, __nv_bfloat16& h, __nv_bfloat16& l) {
    h = __float2bfloat16_rn(x);
    l = __float2bfloat16_rn(x - __bfloat162float(h));
}
__device__ __forceinline__ uint32_t smem_u32(const void* p) {
    uint32_t a;
    asm("{ .reg .u64 t; cvta.to.shared.u64 t, %1; cvt.u32.u64 %0, t; }"
        : "=r"(a) : "l"(p));
    return a;
}

#define CP_ASYNC16(saddr, gaddr) \
    asm volatile("cp.async.cg.shared.global [%0], [%1], 16;" \
                 :: "r"(saddr), "l"(gaddr))
#define CP_COMMIT()  asm volatile("cp.async.commit_group;")
#define CP_WAIT1()   asm volatile("cp.async.wait_group 1;")
#define CP_WAIT0()   asm volatile("cp.async.wait_group 0;")

#define LDSM4(d, addr) \
    asm volatile("ldmatrix.sync.aligned.m8n8.x4.shared.b16 {%0,%1,%2,%3}, [%4];" \
                 : "=r"((d)[0]), "=r"((d)[1]), "=r"((d)[2]), "=r"((d)[3]) \
                 : "r"(addr))

#define MMA16816(cf, a, b0_, b1_) \
    asm volatile("mma.sync.aligned.m16n8k16.row.col.f32.bf16.bf16.f32 " \
                 "{%0,%1,%2,%3}, {%4,%5,%6,%7}, {%8,%9}, {%0,%1,%2,%3};" \
                 : "+f"((cf)[0]), "+f"((cf)[1]), "+f"((cf)[2]), "+f"((cf)[3]) \
                 : "r"((a)[0]), "r"((a)[1]), "r"((a)[2]), "r"((a)[3]), \
                   "r"(b0_), "r"(b1_))

// ---------------------------------------------------------------------------
// HMMA split-GEMM. BM=128, BK=32, 8 warps (4m x 2n), warp tile 32 x (BN/2).
// 2-stage cp.async pipeline, 2 blocks/SM.
// A: [M,K] bf16 (hi,lo). B: [N,K] bf16 (hi,lo; pre-transposed weights).
// ---------------------------------------------------------------------------
template <int BN_, int ACT, int OUT_PAIR>
__global__ void __launch_bounds__(256, 2) hmma_gemm_kernel(
    const __nv_bfloat16* __restrict__ Ah, const __nv_bfloat16* __restrict__ Al,
    const __nv_bfloat16* __restrict__ Bh, const __nv_bfloat16* __restrict__ Bl,
    const float* __restrict__ bias,
    float* __restrict__ C, __nv_bfloat16* __restrict__ Ch, __nv_bfloat16* __restrict__ Cl,
    int M, int N, int K)
{
    constexpr int BM_ = 128;
    constexpr int WCOLS = BN_ / 2;      // cols per warp (64 or 32)
    constexpr int NJ = WCOLS / 8;       // n8 atoms per warp (8 or 4)
    constexpr int NT = NJ / 2;          // n16 ldmatrix tiles (4 or 2)
    constexpr int LDT = 80;             // smem row stride bytes (40 bf16)
    constexpr int A_BYTES = BM_ * LDT;
    constexpr int B_BYTES = BN_ * LDT;
    constexpr int STAGE = 2 * A_BYTES + 2 * B_BYTES;

    extern __shared__ __align__(128) char smem[];
    const uint32_t sb = smem_u32(smem);

    const int tid = threadIdx.x;
    const int wid = tid >> 5;
    const int lane = tid & 31;
    const int wm = wid >> 1;            // 0..3
    const int wn = wid & 1;             // 0..1

    const int bm0 = blockIdx.y * BM_;
    const int bn0 = blockIdx.x * BN_;
    const int NK = K >> 5;              // BK = 32

    const char* gAh = (const char*)(Ah + (size_t)bm0 * K);
    const char* gAl = (const char*)(Al + (size_t)bm0 * K);
    const char* gBh = (const char*)(Bh + (size_t)bn0 * K);
    const char* gBl = (const char*)(Bl + (size_t)bn0 * K);
    const int ldg = K * 2;

    auto load_stage = [&](int slot, int kc) {
        const uint32_t s0 = sb + slot * STAGE;
        const int kb = kc * 64;
        #pragma unroll
        for (int it = 0; it < 2; it++) {            // A: 128 rows x 4 chunks
            int idx = it * 256 + tid;
            int r = idx >> 2, c = (idx & 3) * 16;
            uint32_t so = s0 + r * LDT + c;
            CP_ASYNC16(so, gAh + (size_t)r * ldg + kb + c);
            CP_ASYNC16(so + A_BYTES, gAl + (size_t)r * ldg + kb + c);
        }
        #pragma unroll
        for (int it = 0; it < BN_ / 64; it++) {     // B: BN_ rows x 4 chunks
            int idx = it * 256 + tid;
            int r = idx >> 2, c = (idx & 3) * 16;
            uint32_t so = s0 + 2 * A_BYTES + r * LDT + c;
            CP_ASYNC16(so, gBh + (size_t)r * ldg + kb + c);
            CP_ASYNC16(so + B_BYTES, gBl + (size_t)r * ldg + kb + c);
        }
    };

    const uint32_t aLaneOff =
        (uint32_t)((wm * 32 + (lane & 15)) * LDT + (lane >> 4) * 16);
    const uint32_t bLaneOff =
        (uint32_t)((wn * WCOLS + (lane & 7) + ((lane >> 4) << 3)) * LDT +
                   (((lane >> 3) & 1) << 4));

    float c[2][NJ][4];
    #pragma unroll
    for (int mi = 0; mi < 2; mi++)
        #pragma unroll
        for (int nj = 0; nj < NJ; nj++)
            #pragma unroll
            for (int q = 0; q < 4; q++) c[mi][nj][q] = 0.f;

    load_stage(0, 0);
    CP_COMMIT();

    for (int kc = 0; kc < NK; kc++) {
        if (kc + 1 < NK) load_stage((kc + 1) & 1, kc + 1);
        CP_COMMIT();
        CP_WAIT1();
        __syncthreads();

        const int slot = kc & 1;
        const uint32_t aB = sb + slot * STAGE + aLaneOff;
        const uint32_t bB = sb + slot * STAGE + 2 * A_BYTES + bLaneOff;

        #pragma unroll
        for (int kh = 0; kh < 2; kh++) {
            const uint32_t ko = kh * 32;
            uint32_t ah[2][4], al[2][4];
            #pragma unroll
            for (int mi = 0; mi < 2; mi++) {
                LDSM4(ah[mi], aB + mi * 16 * LDT + ko);
                LDSM4(al[mi], aB + A_BYTES + mi * 16 * LDT + ko);
            }
            #pragma unroll
            for (int t = 0; t < NT; t++) {
                uint32_t bh[4], bl[4];
                LDSM4(bh, bB + t * 16 * LDT + ko);
                LDSM4(bl, bB + B_BYTES + t * 16 * LDT + ko);
                #pragma unroll
                for (int mi = 0; mi < 2; mi++) {
                    MMA16816(c[mi][2 * t + 0], ah[mi], bh[0], bh[1]);
                    MMA16816(c[mi][2 * t + 1], ah[mi], bh[2], bh[3]);
                    MMA16816(c[mi][2 * t + 0], ah[mi], bl[0], bl[1]);
                    MMA16816(c[mi][2 * t + 1], ah[mi], bl[2], bl[3]);
                    MMA16816(c[mi][2 * t + 0], al[mi], bh[0], bh[1]);
                    MMA16816(c[mi][2 * t + 1], al[mi], bh[2], bh[3]);
                }
            }
        }
        __syncthreads();
    }

    CP_WAIT0();
    __syncthreads();

    // ---- epilogue: frags -> smem (pad 33) -> coalesced global ----
    float* eb = (float*)smem;  // [128][33]
    for (int c0 = 0; c0 < BN_; c0 += 32) {
        if (wn == c0 / WCOLS) {
            const int njb = (c0 % WCOLS) >> 3;
            #pragma unroll
            for (int mi = 0; mi < 2; mi++)
                #pragma unroll
                for (int j = 0; j < 4; j++) {
                    int nj = njb + j;
                    int row = wm * 32 + mi * 16 + (lane >> 2);
                    int col = wn * WCOLS + nj * 8 + (lane & 3) * 2 - c0;
                    eb[row * 33 + col]           = c[mi][nj][0];
                    eb[row * 33 + col + 1]       = c[mi][nj][1];
                    eb[(row + 8) * 33 + col]     = c[mi][nj][2];
                    eb[(row + 8) * 33 + col + 1] = c[mi][nj][3];
                }
        }
        __syncthreads();
        #pragma unroll
        for (int it = 0; it < 16; it++) {
            int idx = it * 256 + tid;
            int r = idx >> 5, cc = idx & 31;
            float v = eb[r * 33 + cc];
            int col = bn0 + c0 + cc;
            if (bias) v += bias[col];
            if (ACT == 1) v = gelu_f(v);
            size_t gi = (size_t)(bm0 + r) * N + col;
            if (OUT_PAIR) {
                __nv_bfloat16 h, l;
                split_bf16(v, h, l);
                Ch[gi] = h;
                Cl[gi] = l;
            } else {
                C[gi] = v;
            }
        }
        __syncthreads();
    }
}

// ---------------------------------------------------------------------------
// Weight prep: transpose [512,N] fp32 -> [N,512] bf16 hi/lo, 42 matrices.
// Slot order keeps q,k,v adjacent so fused QKV GEMM sees [1536,512].
// ---------------------------------------------------------------------------
__global__ void __launch_bounds__(256) wprep_kernel(
    const float* __restrict__ wq, const float* __restrict__ wk,
    const float* __restrict__ wv, const float* __restrict__ wp,
    const float* __restrict__ w1, const float* __restrict__ w2,
    const float* __restrict__ wh1, const float* __restrict__ wh2,
    __nv_bfloat16* __restrict__ oh, __nv_bfloat16* __restrict__ ol)
{
    const int z = blockIdx.z;
    const float* src;
    int N = 512;
    if (z < 32) {
        int i = z >> 3, j = z & 7, half = j >> 2, wsel = j & 3;
        const float* base = (wsel == 0) ? wq : (wsel == 1) ? wk : (wsel == 2) ? wv : wp;
        src = base + ((size_t)i * 2 + half) * DD;
    } else if (z < 40) {
        int i = (z - 32) >> 1;
        src = (((z - 32) & 1) ? w2 : w1) + (size_t)i * DD;
    } else if (z == 40) {
        src = wh1;
    } else {
        src = wh2;
        N = 64;
    }
    const int n0 = blockIdx.x * 32, k0 = blockIdx.y * 32;
    if (n0 >= N) return;

    __shared__ float t[32][33];
    const int lx = threadIdx.x & 31, ly = threadIdx.x >> 5;
    for (int r = ly; r < 32; r += 8)
        t[r][lx] = src[(size_t)(k0 + r) * N + n0 + lx];
    __syncthreads();
    const size_t slot = (size_t)z * DD;
    for (int r = ly; r < 32; r += 8) {
        float x = t[lx][r];
        __nv_bfloat16 h, l;
        split_bf16(x, h, l);
        oh[slot + (size_t)(n0 + r) * 512 + k0 + lx] = h;
        ol[slot + (size_t)(n0 + r) * 512 + k0 + lx] = l;
    }
}

__global__ void wae_prep_kernel(const float* __restrict__ w,
                                __nv_bfloat16* __restrict__ oh,
                                __nv_bfloat16* __restrict__ ol)
{
    int idx = blockIdx.x * 256 + threadIdx.x;
    if (idx >= 512 * 128) return;
    int n = idx >> 7, k = idx & 127;
    float x = (k < 65) ? w[(size_t)k * 512 + n] : 0.f;
    __nv_bfloat16 h, l;
    split_bf16(x, h, l);
    oh[idx] = h;
    ol[idx] = l;
}

__global__ void act_prep_kernel(const float* __restrict__ a,
                                __nv_bfloat16* __restrict__ oh,
                                __nv_bfloat16* __restrict__ ol)
{
    int idx = blockIdx.x * 256 + threadIdx.x;
    if (idx >= M_ROWS * 128) return;
    int m = idx >> 7, k = idx & 127;
    float x = (k < 65) ? a[(size_t)m * 65 + k] : 0.f;
    __nv_bfloat16 h, l;
    split_bf16(x, h, l);
    oh[idx] = h;
    ol[idx] = l;
}

// concat biases: row 2i = [bq0|bk0|bv0], row 2i+1 = [bk1|bv1|0]
__global__ void catbias_kernel(const float* __restrict__ bq,
                               const float* __restrict__ bk,
                               const float* __restrict__ bv,
                               float* __restrict__ out)
{
    int idx = blockIdx.x * 256 + threadIdx.x;
    if (idx >= 8 * 1536) return;
    int s = idx / 1536, j = idx % 1536;
    int i = s >> 1, half = s & 1;
    float v;
    if (half == 0) {
        v = (j < 512) ? bq[(i * 2 + 0) * 512 + j]
          : (j < 1024) ? bk[(i * 2 + 0) * 512 + j - 512]
          : bv[(i * 2 + 0) * 512 + j - 1024];
    } else {
        v = (j < 512) ? bk[(i * 2 + 1) * 512 + j]
          : (j < 1024) ? bv[(i * 2 + 1) * 512 + j - 512]
          : 0.f;
    }
    out[idx] = v;
}

__global__ void split_pair_kernel(const float4* __restrict__ in,
                                  __nv_bfloat162* __restrict__ oh,
                                  __nv_bfloat162* __restrict__ ol, int n4)
{
    int i = blockIdx.x * 256 + threadIdx.x;
    if (i >= n4) return;
    float4 x = in[i];
    __nv_bfloat16 h0, l0, h1, l1, h2, l2, h3, l3;
    split_bf16(x.x, h0, l0);
    split_bf16(x.y, h1, l1);
    split_bf16(x.z, h2, l2);
    split_bf16(x.w, h3, l3);
    oh[i * 2 + 0] = __nv_bfloat162(h0, h1);
    oh[i * 2 + 1] = __nv_bfloat162(h2, h3);
    ol[i * 2 + 0] = __nv_bfloat162(l0, l1);
    ol[i * 2 + 1] = __nv_bfloat162(l2, l3);
}

// ---------------------------------------------------------------------------
// Fused attention: one block per (b,h), 64x64 tile; strided q/k/v inputs.
// Output written directly as bf16 hi/lo split pair (feeds the P projection).
// ---------------------------------------------------------------------------
#define APAD 68

__global__ void __launch_bounds__(256) attn_kernel(
    const float* __restrict__ q, int ldq,
    const float* __restrict__ k, int ldk,
    const float* __restrict__ v, int ldv,
    __nv_bfloat16* __restrict__ yh, __nv_bfloat16* __restrict__ yl)
{
    extern __shared__ float sm[];
    float* sq  = sm;
    float* skT = sm + 64 * APAD;
    float* sv  = sm + 2 * 64 * APAD;

    const int bh = blockIdx.x;
    const int b = bh >> 3, h = bh & 7;
    const int row0 = b * 64;
    const int hc = h * 64;
    const int tid = threadIdx.x;

    for (int i = tid; i < 4096; i += 256) {
        int r = i >> 6, c = i & 63;
        sq[r * APAD + c]  = q[(size_t)(row0 + r) * ldq + hc + c];
        skT[c * APAD + r] = k[(size_t)(row0 + r) * ldk + hc + c];
        sv[r * APAD + c]  = v[(size_t)(row0 + r) * ldv + hc + c];
    }
    __syncthreads();

    const int r  = tid >> 2;
    const int c0 = (tid & 3) * 16;

    float acc[16];
    #pragma unroll
    for (int j = 0; j < 16; j++) acc[j] = 0.f;
    for (int kk = 0; kk < 64; kk++) {
        float qv = sq[r * APAD + kk];
        #pragma unroll
        for (int j = 0; j < 16; j++)
            acc[j] += qv * skT[kk * APAD + c0 + j];
    }

    float mx = -1e30f;
    #pragma unroll
    for (int j = 0; j < 16; j++) {
        int c = c0 + j;
        acc[j] = (c <= r) ? acc[j] * 0.125f : -1e30f;
        mx = fmaxf(mx, acc[j]);
    }
    mx = fmaxf(mx, __shfl_xor_sync(0xFFFFFFFFu, mx, 1));
    mx = fmaxf(mx, __shfl_xor_sync(0xFFFFFFFFu, mx, 2));

    float sum = 0.f;
    #pragma unroll
    for (int j = 0; j < 16; j++) {
        acc[j] = expf(acc[j] - mx);
        sum += acc[j];
    }
    sum += __shfl_xor_sync(0xFFFFFFFFu, sum, 1);
    sum += __shfl_xor_sync(0xFFFFFFFFu, sum, 2);
    float inv = 1.f / sum;

    __syncthreads();
    #pragma unroll
    for (int j = 0; j < 16; j++)
        sq[r * APAD + c0 + j] = acc[j] * inv;
    __syncthreads();

    float out[16];
    #pragma unroll
    for (int j = 0; j < 16; j++) out[j] = 0.f;
    for (int kk = 0; kk < 64; kk++) {
        float a = sq[r * APAD + kk];
        #pragma unroll
        for (int j = 0; j < 16; j++)
            out[j] += a * sv[kk * APAD + c0 + j];
    }
    #pragma unroll
    for (int j = 0; j < 16; j++) {
        size_t gi = (size_t)(row0 + r) * DMODEL + hc + c0 + j;
        __nv_bfloat16 hh, ll;
        split_bf16(out[j], hh, ll);
        yh[gi] = hh;
        yl[gi] = ll;
    }
}

// ---------------------------------------------------------------------------
// Fused (x+res) -> LayerNorm, writes fp32 + bf16 hi/lo pair.
// ---------------------------------------------------------------------------
__global__ void __launch_bounds__(128) add_ln_kernel(
    const float* __restrict__ x, const float* __restrict__ res,
    const float* __restrict__ g, const float* __restrict__ bb,
    float* __restrict__ out,
    __nv_bfloat16* __restrict__ oh, __nv_bfloat16* __restrict__ ol)
{
    const int row = blockIdx.x;
    const int tid = threadIdx.x;
    const float* xr = x + (size_t)row * DMODEL;
    const float* rr = res ? res + (size_t)row * DMODEL : nullptr;

    float v[4];
    float s = 0.f;
    #pragma unroll
    for (int i = 0; i < 4; i++) {
        int c = tid + i * 128;
        float t = xr[c];
        if (rr) t += rr[c];
        v[i] = t;
        s += t;
    }

    __shared__ float red[4];
    #pragma unroll
    for (int o = 16; o; o >>= 1) s += __shfl_xor_sync(0xFFFFFFFFu, s, o);
    if ((tid & 31) == 0) red[tid >> 5] = s;
    __syncthreads();
    s = red[0] + red[1] + red[2] + red[3];
    const float mu = s * (1.f / 512.f);

    float var = 0.f;
    #pragma unroll
    for (int i = 0; i < 4; i++) {
        float d = v[i] - mu;
        var += d * d;
    }
    #pragma unroll
    for (int o = 16; o; o >>= 1) var += __shfl_xor_sync(0xFFFFFFFFu, var, o);
    __syncthreads();
    if ((tid & 31) == 0) red[tid >> 5] = var;
    __syncthreads();
    var = (red[0] + red[1] + red[2] + red[3]) * (1.f / 512.f);
    const float rs = rsqrtf(var + 1e-5f);

    #pragma unroll
    for (int i = 0; i < 4; i++) {
        int c = tid + i * 128;
        float val = (v[i] - mu) * rs * g[c] + bb[c];
        size_t gi = (size_t)row * DMODEL + c;
        out[gi] = val;
        __nv_bfloat16 h, l;
        split_bf16(val, h, l);
        oh[gi] = h;
        ol[gi] = l;
    }
}

// ---------------------------------------------------------------------------
// Host orchestration
// ---------------------------------------------------------------------------
template <int BN_, int ACT, int OUT_PAIR>
static void launch_hmma(const __nv_bfloat16* Ah, const __nv_bfloat16* Al,
                        const __nv_bfloat16* Bh, const __nv_bfloat16* Bl,
                        const float* bias, float* C,
                        __nv_bfloat16* Ch, __nv_bfloat16* Cl,
                        int M, int N, int K)
{
    constexpr int STAGE = (2 * 128 + 2 * BN_) * 80;
    const int sbytes = 2 * STAGE;
    cudaFuncSetAttribute(hmma_gemm_kernel<BN_, ACT, OUT_PAIR>,
                         cudaFuncAttributeMaxDynamicSharedMemorySize, sbytes);
    dim3 grid(N / BN_, M / 128);
    hmma_gemm_kernel<BN_, ACT, OUT_PAIR><<<grid, 256, sbytes>>>(
        Ah, Al, Bh, Bl, bias, C, Ch, Cl, M, N, K);
}

extern "C" void kernel_launch(void* const* d_in, const int* in_sizes, int n_in,
                              void* d_out, int out_size)
{
    const float* action   = (const float*)d_in[0];
    const float* obs_rep  = (const float*)d_in[1];
    const float* w_ae     = (const float*)d_in[3];
    const float* ln0_g    = (const float*)d_in[4];
    const float* ln0_b    = (const float*)d_in[5];
    const float* blk_ln_g = (const float*)d_in[6];
    const float* blk_ln_b = (const float*)d_in[7];
    const float* blk_wq   = (const float*)d_in[8];
    const float* blk_wk   = (const float*)d_in[9];
    const float* blk_wv   = (const float*)d_in[10];
    const float* blk_wp   = (const float*)d_in[11];
    const float* blk_bq   = (const float*)d_in[12];
    const float* blk_bk   = (const float*)d_in[13];
    const float* blk_bv   = (const float*)d_in[14];
    const float* blk_bp   = (const float*)d_in[15];
    const float* blk_w1   = (const float*)d_in[16];
    const float* blk_b1   = (const float*)d_in[17];
    const float* blk_w2   = (const float*)d_in[18];
    const float* blk_b2   = (const float*)d_in[19];
    const float* wh1      = (const float*)d_in[20];
    const float* bh1      = (const float*)d_in[21];
    const float* lnh_g    = (const float*)d_in[22];
    const float* lnh_b    = (const float*)d_in[23];
    const float* wh2      = (const float*)d_in[24];
    const float* bh2      = (const float*)d_in[25];

    float *X, *T, *Q1, *QKV, *CatB;
    __nv_bfloat16 *Ph, *Pl, *P2h, *P2l, *Oh, *Ol, *Wh, *Wl, *AEh, *AEl, *WAEh, *WAEl;
    cudaGetSymbolAddress((void**)&X, g_X);
    cudaGetSymbolAddress((void**)&T, g_T);
    cudaGetSymbolAddress((void**)&Q1, g_Q1);
    cudaGetSymbolAddress((void**)&QKV, g_QKV);
    cudaGetSymbolAddress((void**)&CatB, g_CatB);
    cudaGetSymbolAddress((void**)&Ph, g_Ph);
    cudaGetSymbolAddress((void**)&Pl, g_Pl);
    cudaGetSymbolAddress((void**)&P2h, g_P2h);
    cudaGetSymbolAddress((void**)&P2l, g_P2l);
    cudaGetSymbolAddress((void**)&Oh, g_Oh);
    cudaGetSymbolAddress((void**)&Ol, g_Ol);
    cudaGetSymbolAddress((void**)&Wh, g_Wh);
    cudaGetSymbolAddress((void**)&Wl, g_Wl);
    cudaGetSymbolAddress((void**)&AEh, g_AEh);
    cudaGetSymbolAddress((void**)&AEl, g_AEl);
    cudaGetSymbolAddress((void**)&WAEh, g_WAEh);
    cudaGetSymbolAddress((void**)&WAEl, g_WAEl);

    const int attn_smem = 3 * 64 * APAD * 4;
    cudaFuncSetAttribute(attn_kernel,
                         cudaFuncAttributeMaxDynamicSharedMemorySize, attn_smem);

    const int M = M_ROWS, D = DMODEL;
    const int n4 = M * D / 4;

    // ---- prep ----
    {
        dim3 g(16, 16, 42);
        wprep_kernel<<<g, 256>>>(blk_wq, blk_wk, blk_wv, blk_wp,
                                 blk_w1, blk_w2, wh1, wh2, Wh, Wl);
        wae_prep_kernel<<<(512 * 128 + 255) / 256, 256>>>(w_ae, WAEh, WAEl);
        act_prep_kernel<<<(M * 128 + 255) / 256, 256>>>(action, AEh, AEl);
        catbias_kernel<<<(8 * 1536 + 255) / 256, 256>>>(blk_bq, blk_bk, blk_bv, CatB);
        split_pair_kernel<<<(n4 + 255) / 256, 256>>>(
            (const float4*)obs_rep, (__nv_bfloat162*)Oh, (__nv_bfloat162*)Ol, n4);
    }

    // ---- encoder: X = LN(gelu(action @ w_ae)) ----
    launch_hmma<128, 1, 0>(AEh, AEl, WAEh, WAEl, nullptr, T, nullptr, nullptr, M, D, 128);
    add_ln_kernel<<<M, 128>>>(T, nullptr, ln0_g, ln0_b, X, Ph, Pl);

    for (int i = 0; i < 4; i++) {
        const __nv_bfloat16* wqkv0h = Wh + (size_t)(i * 8 + 0) * DD;  // q,k,v adjacent
        const __nv_bfloat16* wqkv0l = Wl + (size_t)(i * 8 + 0) * DD;
        const __nv_bfloat16* wp0h   = Wh + (size_t)(i * 8 + 3) * DD;
        const __nv_bfloat16* wp0l   = Wl + (size_t)(i * 8 + 3) * DD;
        const __nv_bfloat16* wq1h   = Wh + (size_t)(i * 8 + 4) * DD;
        const __nv_bfloat16* wq1l   = Wl + (size_t)(i * 8 + 4) * DD;
        const __nv_bfloat16* wkv1h  = Wh + (size_t)(i * 8 + 5) * DD;  // k,v adjacent
        const __nv_bfloat16* wkv1l  = Wl + (size_t)(i * 8 + 5) * DD;
        const __nv_bfloat16* wp1h   = Wh + (size_t)(i * 8 + 7) * DD;
        const __nv_bfloat16* wp1l   = Wl + (size_t)(i * 8 + 7) * DD;
        const __nv_bfloat16* w1h    = Wh + (size_t)(32 + i * 2) * DD;
        const __nv_bfloat16* w1l    = Wl + (size_t)(32 + i * 2) * DD;
        const __nv_bfloat16* w2h    = Wh + (size_t)(33 + i * 2) * DD;
        const __nv_bfloat16* w2l    = Wl + (size_t)(33 + i * 2) * DD;

        const float* cb0 = CatB + (size_t)(2 * i + 0) * 1536;
        const float* cb1 = CatB + (size_t)(2 * i + 1) * 1536;
        const float* bq1 = blk_bq + ((size_t)i * 2 + 1) * D;
        const float* bp0 = blk_bp + ((size_t)i * 2 + 0) * D;
        const float* bp1 = blk_bp + ((size_t)i * 2 + 1) * D;
        const float* g0 = blk_ln_g + ((size_t)i * 3 + 0) * D;
        const float* b0 = blk_ln_b + ((size_t)i * 3 + 0) * D;
        const float* g1 = blk_ln_g + ((size_t)i * 3 + 1) * D;
        const float* b1 = blk_ln_b + ((size_t)i * 3 + 1) * D;
        const float* g2 = blk_ln_g + ((size_t)i * 3 + 2) * D;
        const float* b2 = blk_ln_b + ((size_t)i * 3 + 2) * D;
        const float* bias1 = blk_b1 + (size_t)i * D;
        const float* bias2 = blk_b2 + (size_t)i * D;

        // sublayer 1: fused QKV projection, self-attn (attn writes split pair)
        launch_hmma<128, 0, 0>(Ph, Pl, wqkv0h, wqkv0l, cb0, QKV, nullptr, nullptr, M, 1536, D);
        attn_kernel<<<2048, 256, attn_smem>>>(QKV, 1536, QKV + 512, 1536, QKV + 1024, 1536, Ph, Pl);
        launch_hmma<128, 0, 0>(Ph, Pl, wp0h, wp0l, bp0, T, nullptr, nullptr, M, D, D);
        add_ln_kernel<<<M, 128>>>(T, X, g0, b0, X, Ph, Pl);

        // sublayer 2: cross-attn (q = obs_rep proj; fused KV)
        launch_hmma<128, 0, 0>(Oh, Ol, wq1h, wq1l, bq1, Q1, nullptr, nullptr, M, D, D);
        launch_hmma<128, 0, 0>(Ph, Pl, wkv1h, wkv1l, cb1, QKV, nullptr, nullptr, M, 1024, D);
        attn_kernel<<<2048, 256, attn_smem>>>(Q1, 512, QKV, 1024, QKV + 512, 1024, Ph, Pl);
        launch_hmma<128, 0, 0>(Ph, Pl, wp1h, wp1l, bp1, T, nullptr, nullptr, M, D, D);
        add_ln_kernel<<<M, 128>>>(T, obs_rep, g1, b1, X, Ph, Pl);

        // sublayer 3: MLP
        launch_hmma<128, 1, 1>(Ph, Pl, w1h, w1l, bias1, nullptr, P2h, P2l, M, D, D);
        launch_hmma<128, 0, 0>(P2h, P2l, w2h, w2l, bias2, T, nullptr, nullptr, M, D, D);
        add_ln_kernel<<<M, 128>>>(T, X, g2, b2, X, Ph, Pl);
    }

    // head
    const __nv_bfloat16* wh1h = Wh + (size_t)40 * DD;
    const __nv_bfloat16* wh1l = Wl + (size_t)40 * DD;
    const __nv_bfloat16* wh2h = Wh + (size_t)41 * DD;
    const __nv_bfloat16* wh2l = Wl + (size_t)41 * DD;
    launch_hmma<128, 1, 0>(Ph, Pl, wh1h, wh1l, bh1, T, nullptr, nullptr, M, D, D);
    add_ln_kernel<<<M, 128>>>(T, nullptr, lnh_g, lnh_b, Q1, Ph, Pl);
    launch_hmma<64, 0, 0>(Ph, Pl, wh2h, wh2l, bh2, (float*)d_out, nullptr, nullptr, M, 64, D);
}